// round 13
// baseline (speedup 1.0000x reference)
#include <cuda_runtime.h>
#include <cuda_bf16.h>
#include <cuda_fp16.h>
#include <cstdint>
#include <cstddef>

#define NB 2
#define C_ 256
#define CI_ 128
#define NNPOS 65536
#define NCH1 49            // uneven k-chunks, pass1: 3 quads x 49 x 2 b = 294 CTAs
#define NT2 64             // spatial cols per pass2 tile
#define UNITS 2048         // NB * 1024 ntiles (full 256 m per unit)
#define TPC 14             // units per CTA pass2 -> 147 CTAs (one wave)
#define CHAIN_BLOCKS 258

// ---------------- scratch (static device globals; no allocation) ----------------
__device__ __align__(16) __half   d_xh[(size_t)NB * C_ * NNPOS];       // x in fp16 (67MB)
__device__ __align__(16) float    d_Sp[(size_t)NB * NCH1 * 3 * 16384]; // partial S
__device__ __align__(16) float    d_S[NB * C_ * C_];
__device__ __align__(16) float    d_s[NB * C_];
__device__ __align__(16) float    d_gwT[C_ * CI_];        // g_w transposed [d][j]
__device__ __align__(16) float    d_T1[NB * CI_ * C_];
__device__ __align__(16) float    d_u[NB * CI_];
__device__ __align__(16) float    d_v[NB * CI_];
__device__ __align__(16) float    d_kvT[NB * CI_ * CI_];  // kv transposed [b][j][i]
__device__ __align__(16) float    d_b2[NB * C_];
__device__ __align__(16) uint32_t d_Ah16[NB * C_ * CI_];  // A fp16x2 [b][m][kpair]
__device__ unsigned d_cnt = 0;
__device__ unsigned d_gen = 0;

// ---------------- primitives ----------------
__device__ __forceinline__ uint32_t smem_u32(const void* p) {
    uint32_t a;
    asm("{ .reg .u64 t; cvta.to.shared.u64 t, %1; cvt.u32.u64 %0, t; }" : "=r"(a) : "l"(p));
    return a;
}
__device__ __forceinline__ void mma16816h(float* d, const uint32_t* a, const uint32_t* b) {
    asm volatile("mma.sync.aligned.m16n8k16.row.col.f32.f16.f16.f32 "
                 "{%0,%1,%2,%3}, {%4,%5,%6,%7}, {%8,%9}, {%0,%1,%2,%3};"
                 : "+f"(d[0]), "+f"(d[1]), "+f"(d[2]), "+f"(d[3])
                 : "r"(a[0]), "r"(a[1]), "r"(a[2]), "r"(a[3]), "r"(b[0]), "r"(b[1]));
}
__device__ __forceinline__ void ldsm4(uint32_t* r, uint32_t addr) {
    asm volatile("ldmatrix.sync.aligned.m8n8.x4.shared.b16 {%0,%1,%2,%3}, [%4];"
                 : "=r"(r[0]), "=r"(r[1]), "=r"(r[2]), "=r"(r[3]) : "r"(addr));
}
__device__ __forceinline__ void ldsm4t(uint32_t* r, uint32_t addr) {
    asm volatile("ldmatrix.sync.aligned.m8n8.x4.trans.shared.b16 {%0,%1,%2,%3}, [%4];"
                 : "=r"(r[0]), "=r"(r[1]), "=r"(r[2]), "=r"(r[3]) : "r"(addr));
}
__device__ __forceinline__ uint32_t sw128(uint32_t byte) { return byte ^ ((byte >> 3) & 0x70u); }
__device__ __forceinline__ uint32_t sw512(uint32_t byte) { return byte ^ ((byte >> 5) & 0x70u); }

__device__ __forceinline__ uint32_t packh(float x, float y) {
    __half2 h = __floats2half2_rn(x, y);
    return *(uint32_t*)&h;
}
__device__ __forceinline__ float4 f4fma(float s, float4 q, float4 a) {
    a.x += s * q.x; a.y += s * q.y; a.z += s * q.z; a.w += s * q.w;
    return a;
}
__device__ __forceinline__ void cpasync16(uint32_t dst, const void* src) {
    asm volatile("cp.async.cg.shared.global [%0], [%1], 16;" :: "r"(dst), "l"(src));
}
#define CP_COMMIT() asm volatile("cp.async.commit_group;" ::: "memory")
#define CP_WAIT2()  asm volatile("cp.async.wait_group 2;" ::: "memory")

// grid-wide barrier (sense via monotonically increasing generation; replay-safe)
__device__ __forceinline__ void gridbar() {
    __syncthreads();
    if (threadIdx.x == 0) {
        __threadfence();
        unsigned g = *(volatile unsigned*)&d_gen;
        unsigned old = atomicAdd(&d_cnt, 1);
        if (old == CHAIN_BLOCKS - 1) {
            d_cnt = 0;
            __threadfence();
            atomicAdd(&d_gen, 1);
        } else {
            while (*(volatile unsigned*)&d_gen == g) { }
        }
        __threadfence();
    }
    __syncthreads();
}

extern __shared__ uint8_t dsm[];

// ================= prepass: x -> fp16 xh, rowsums =================
__global__ __launch_bounds__(256) void prepass_kernel(const float* __restrict__ x) {
    int row = blockIdx.x;                 // 0..511 = b*C_+c
    const float4* src = (const float4*)(x + (size_t)row * NNPOS);
    uint2* dst = (uint2*)(d_xh + (size_t)row * NNPOS);
    int t = threadIdx.x;
    float rs = 0.f;
#pragma unroll 4
    for (int i = t; i < NNPOS / 4; i += 256) {
        float4 v = src[i];
        rs += v.x + v.y + v.z + v.w;
        dst[i] = make_uint2(packh(v.x, v.y), packh(v.z, v.w));
    }
    __shared__ float red[256];
    red[t] = rs;
    __syncthreads();
    for (int s = 128; s > 0; s >>= 1) {
        if (t < s) red[t] += red[t + s];
        __syncthreads();
    }
    if (t == 0) d_s[row] = red[0];
}

// ================= pass 1: 3-quadrant syrk, cp.async 3-stage pipeline ============
// grid (3, NCH1, NB), block 256; smem = 3 stages x 32KB (A 16KB | B 16KB)
__global__ __launch_bounds__(256, 2) void pass1_kernel() {
    int qi = blockIdx.x, ch = blockIdx.y, b = blockIdx.z;
    int qm = qi >> 1, qn = (qi + 1) >> 1;   // 0:(0,0) 1:(0,1) 2:(1,1)
    bool diag = (qi != 1);
    int kt0 = (ch * 1024) / NCH1, kt1 = ((ch + 1) * 1024) / NCH1;
    const __half* xa = d_xh + ((size_t)(b * C_ + qm * 128)) * NNPOS;
    const __half* xb = d_xh + ((size_t)(b * C_ + qn * 128)) * NNPOS;

    int t = threadIdx.x, w = t >> 5, lane = t & 31;
    int wm = w >> 1, wn = w & 1;
    int m0 = wm * 32, n0 = wn * 64;
    uint32_t sbase = smem_u32(dsm);

    float acc[2][8][4];
#pragma unroll
    for (int i = 0; i < 2; i++)
#pragma unroll
        for (int j = 0; j < 8; j++)
#pragma unroll
            for (int q = 0; q < 4; q++) acc[i][j][q] = 0.f;

    auto load_tile = [&](int kt, int s) {
        uint32_t stA = sbase + (uint32_t)s * 32768u;
#pragma unroll
        for (int i = 0; i < 4; i++) {
            int c = i * 256 + t;
            int row = c >> 3, col16 = c & 7;
            cpasync16(stA + sw128((uint32_t)row * 128u + (uint32_t)col16 * 16u),
                      xa + (size_t)row * NNPOS + kt * 64 + col16 * 8);
        }
        if (!diag) {
            uint32_t stB = stA + 16384u;
#pragma unroll
            for (int i = 0; i < 4; i++) {
                int c = i * 256 + t;
                int row = c >> 3, col16 = c & 7;
                cpasync16(stB + sw128((uint32_t)row * 128u + (uint32_t)col16 * 16u),
                          xb + (size_t)row * NNPOS + kt * 64 + col16 * 8);
            }
        }
    };

    int nkt = kt1 - kt0;
    load_tile(kt0, 0); CP_COMMIT();
    if (nkt > 1) load_tile(kt0 + 1, 1);
    CP_COMMIT();

    for (int i = 0; i < nkt; i++) {
        if (i + 2 < nkt) load_tile(kt0 + i + 2, (i + 2) % 3);
        CP_COMMIT();                       // always one group per iter (may be empty)
        CP_WAIT2();                        // tile i resident
        __syncthreads();
        uint32_t ahb = sbase + (uint32_t)(i % 3) * 32768u;
        uint32_t bhb = diag ? ahb : ahb + 16384u;
#pragma unroll
        for (int ks = 0; ks < 4; ks++) {
            int k0 = ks * 16;
            uint32_t ah[2][4];
#pragma unroll
            for (int mt = 0; mt < 2; mt++) {
                uint32_t byte = (uint32_t)(m0 + mt * 16 + (lane & 15)) * 128u
                              + (uint32_t)(k0 + (lane >> 4) * 8) * 2u;
                ldsm4(ah[mt], ahb + sw128(byte));
            }
            uint32_t bf[8][2];
            int g = lane >> 3, j = lane & 7;
#pragma unroll
            for (int n2 = 0; n2 < 4; n2++) {
                uint32_t row = (uint32_t)(n0 + n2 * 16 + (g >> 1) * 8 + j);
                uint32_t kk  = (uint32_t)(k0 + (g & 1) * 8);
                uint32_t r[4];
                ldsm4(r, bhb + sw128(row * 128u + kk * 2u));
                bf[n2 * 2][0] = r[0]; bf[n2 * 2][1] = r[1];
                bf[n2 * 2 + 1][0] = r[2]; bf[n2 * 2 + 1][1] = r[3];
            }
#pragma unroll
            for (int mt = 0; mt < 2; mt++)
#pragma unroll
                for (int nt = 0; nt < 8; nt++)
                    mma16816h(acc[mt][nt], ah[mt], bf[nt]);
        }
        __syncthreads();
    }

    float* Sp = d_Sp + (((size_t)(b * NCH1 + ch) * 3 + qi) << 14);
#pragma unroll
    for (int mt = 0; mt < 2; mt++) {
        int r = m0 + mt * 16 + (lane >> 2);
        int c = n0 + 2 * (lane & 3);
#pragma unroll
        for (int nt = 0; nt < 8; nt++) {
            *(float2*)(Sp + (size_t)r * 128 + c + nt * 8)
                = make_float2(acc[mt][nt][0], acc[mt][nt][1]);
            *(float2*)(Sp + (size_t)(r + 8) * 128 + c + nt * 8)
                = make_float2(acc[mt][nt][2], acc[mt][nt][3]);
        }
    }
}

// ================= chain: reduce+mirror+gwt | stageA | stageB | stageC+D =========
__global__ __launch_bounds__(256, 2) void chain_kernel(
    const float* __restrict__ g_w, const float* __restrict__ phi_w,
    const float* __restrict__ g_b, const float* __restrict__ phi_b,
    const float* __restrict__ W_w, const float* __restrict__ theta_w,
    const float* __restrict__ theta_b, const float* __restrict__ W_b) {
    __shared__ __align__(16) uint8_t shraw[8448];
    int bx = blockIdx.x, t = threadIdx.x;

    // ---------- phase 1: reduce partial S (+mirror), gwt transpose ---------------
    if (bx < 96) {
        int id = bx * 256 + t;
        int b = id / 12288, rest = id % 12288;
        int slot = rest >> 12, idx4 = rest & 4095;
        const float4* p = (const float4*)d_Sp;
        size_t base = ((size_t)b * NCH1 * 3 + slot) * 4096 + idx4;
        float4 a = make_float4(0.f, 0.f, 0.f, 0.f);
#pragma unroll 7
        for (int ch = 0; ch < NCH1; ch++) {
            float4 v = p[base + (size_t)ch * 3 * 4096];
            a.x += v.x; a.y += v.y; a.z += v.z; a.w += v.w;
        }
        int ml = idx4 >> 5, c4 = idx4 & 31;
        int m = (slot == 2) ? 128 + ml : ml;
        int n4 = (slot == 0) ? c4 : 32 + c4;
        ((float4*)d_S)[(size_t)b * 16384 + m * 64 + n4] = a;
        if (slot == 1) {                       // mirror quad(1,0) = quad(0,1)^T
            float* Sb = d_S + (size_t)b * 65536;
            int nb = 128 + c4 * 4;
            Sb[(size_t)(nb + 0) * 256 + ml] = a.x;
            Sb[(size_t)(nb + 1) * 256 + ml] = a.y;
            Sb[(size_t)(nb + 2) * 256 + ml] = a.z;
            Sb[(size_t)(nb + 3) * 256 + ml] = a.w;
        }
    } else if (bx < 128) {                     // gwt: transpose g_w -> d_gwT
        float (*tile)[33] = (float (*)[33])shraw;
        int tb = bx - 96;
        int rt = tb >> 3, ct = tb & 7;
        int ty = t >> 5, tx = t & 31;
#pragma unroll
        for (int p = 0; p < 4; p++)
            tile[p * 8 + ty][tx] = g_w[(rt * 32 + p * 8 + ty) * C_ + ct * 32 + tx];
        __syncthreads();
#pragma unroll
        for (int p = 0; p < 4; p++)
            d_gwT[(ct * 32 + p * 8 + ty) * CI_ + rt * 32 + tx] = tile[tx][p * 8 + ty];
    }
    gridbar();

    // ---------- phase 2: stageA (T1 = phi_w @ S ; u,v) ---------------------------
    {
        int i = bx >> 1, b = bx & 1;
        if (i < CI_) {
            float* ph = (float*)shraw;
            float4 (*red)[64] = (float4 (*)[64])(shraw + 1024);
            ph[t] = phi_w[i * C_ + t];
            __syncthreads();
            int kq = t >> 6, jv = t & 63;
            const float4* S4 = (const float4*)(d_S + (size_t)b * 65536);
            float4 a = make_float4(0.f, 0.f, 0.f, 0.f);
#pragma unroll 8
            for (int c = kq * 64; c < kq * 64 + 64; c++)
                a = f4fma(ph[c], S4[c * 64 + jv], a);
            red[kq][jv] = a;
            __syncthreads();
            if (kq == 0) {
                float4 s0 = red[0][jv], s1 = red[1][jv], s2 = red[2][jv], s3 = red[3][jv];
                float4 o;
                o.x = s0.x + s1.x + s2.x + s3.x; o.y = s0.y + s1.y + s2.y + s3.y;
                o.z = s0.z + s1.z + s2.z + s3.z; o.w = s0.w + s1.w + s2.w + s3.w;
                ((float4*)(d_T1 + ((size_t)b * CI_ + i) * C_))[jv] = o;
            }
        } else if (i == CI_) {
            float* ss = (float*)shraw;
            ss[t] = d_s[b * C_ + t];
            __syncthreads();
            int hf = t >> 7, ii = t & 127;
            const float4* wr = (const float4*)((hf ? g_w : phi_w) + ii * C_);
            const float4* sv = (const float4*)ss;
            float acc = 0.f;
#pragma unroll 8
            for (int q = 0; q < 64; q++) {
                float4 wv = wr[q], s4 = sv[q];
                acc += wv.x * s4.x + wv.y * s4.y + wv.z * s4.z + wv.w * s4.w;
            }
            if (hf) d_v[b * CI_ + ii] = acc; else d_u[b * CI_ + ii] = acc;
        }
    }
    gridbar();

    // ---------- phase 3: stageB (kvT) --------------------------------------------
    if (bx < 256) {
        int i = bx >> 1, b = bx & 1;
        float* t1 = (float*)shraw;
        float4 (*red)[32] = (float4 (*)[32])(shraw + 1024);
        t1[t] = d_T1[((size_t)b * CI_ + i) * C_ + t];
        __syncthreads();
        int kq = t >> 5, jv = t & 31;
        const float4* Q = (const float4*)d_gwT;
        float4 a = make_float4(0.f, 0.f, 0.f, 0.f);
#pragma unroll 8
        for (int d = kq * 32; d < kq * 32 + 32; d++)
            a = f4fma(t1[d], Q[d * 32 + jv], a);
        red[kq][jv] = a;
        __syncthreads();
        if (kq == 0) {
            float4 o = make_float4(0.f, 0.f, 0.f, 0.f);
#pragma unroll
            for (int q = 0; q < 8; q++) {
                float4 v = red[q][jv];
                o.x += v.x; o.y += v.y; o.z += v.z; o.w += v.w;
            }
            float ui = d_u[b * CI_ + i], pb = phi_b[i];
            float4 gb = ((const float4*)g_b)[jv];
            float4 vv = ((const float4*)(d_v + b * CI_))[jv];
            o.x += ui * gb.x + pb * vv.x + 65536.0f * pb * gb.x;
            o.y += ui * gb.y + pb * vv.y + 65536.0f * pb * gb.y;
            o.z += ui * gb.z + pb * vv.z + 65536.0f * pb * gb.z;
            o.w += ui * gb.w + pb * vv.w + 65536.0f * pb * gb.w;
            float* kt = d_kvT + (size_t)b * CI_ * CI_;
            kt[(jv * 4 + 0) * CI_ + i] = o.x;
            kt[(jv * 4 + 1) * CI_ + i] = o.y;
            kt[(jv * 4 + 2) * CI_ + i] = o.z;
            kt[(jv * 4 + 3) * CI_ + i] = o.w;
        }
    }
    gridbar();

    // ---------- phase 4: stageC+D fused (per m-row) ------------------------------
    if (bx < 256) {
        int m = bx;
        float*  ww   = (float*)shraw;
        float4 (*red)[32] = (float4 (*)[32])(shraw + 512);
        float*  mmv  = (float*)(shraw + 4608);
        float*  bred = (float*)(shraw + 5120);
        float4 (*redD)[64] = (float4 (*)[64])(shraw + 512);
        for (int b = 0; b < NB; b++) {
            if (t < CI_) ww[t] = W_w[m * CI_ + t];
            __syncthreads();
            int kq = t >> 5, iv = t & 31;
            const float4* Q = (const float4*)(d_kvT + (size_t)b * CI_ * CI_);
            float4 a = make_float4(0.f, 0.f, 0.f, 0.f);
#pragma unroll 8
            for (int j = kq * 16; j < kq * 16 + 16; j++)
                a = f4fma(ww[j], Q[j * 32 + iv], a);
            red[kq][iv] = a;
            __syncthreads();
            if (kq == 0) {
                float4 o = make_float4(0.f, 0.f, 0.f, 0.f);
#pragma unroll
                for (int q = 0; q < 8; q++) {
                    float4 v = red[q][iv];
                    o.x += v.x; o.y += v.y; o.z += v.z; o.w += v.w;
                }
                const float inv = 1.0f / 65536.0f;
                mmv[iv * 4 + 0] = o.x * inv;
                mmv[iv * 4 + 1] = o.y * inv;
                mmv[iv * 4 + 2] = o.z * inv;
                mmv[iv * 4 + 3] = o.w * inv;
            }
            __syncthreads();
            int kq2 = t >> 6, jv2 = t & 63;
            const float4* Qt = (const float4*)theta_w;
            float4 ad = make_float4(0.f, 0.f, 0.f, 0.f);
#pragma unroll 8
            for (int i = kq2 * 32; i < kq2 * 32 + 32; i++)
                ad = f4fma(mmv[i], Qt[i * 64 + jv2], ad);
            redD[kq2][jv2] = ad;
            if (t < CI_) bred[t] = mmv[t] * theta_b[t];
            __syncthreads();
            if (kq2 == 0) {
                float4 s0 = redD[0][jv2], s1 = redD[1][jv2], s2 = redD[2][jv2], s3 = redD[3][jv2];
                float a0 = s0.x + s1.x + s2.x + s3.x, a1 = s0.y + s1.y + s2.y + s3.y;
                float a2 = s0.z + s1.z + s2.z + s3.z, a3 = s0.w + s1.w + s2.w + s3.w;
                size_t base = ((size_t)b * C_ + m) * CI_ + jv2 * 2;
                d_Ah16[base]     = packh(a0, a1);
                d_Ah16[base + 1] = packh(a2, a3);
            }
            for (int s2v = 64; s2v > 0; s2v >>= 1) {
                if (t < s2v) bred[t] += bred[t + s2v];
                __syncthreads();
            }
            if (t == 0) d_b2[b * C_ + m] = bred[0] + W_b[m];
            __syncthreads();
        }
    }
}

// ================= pass 2: out = x + A x + b2 (full A resident, X read once) =====
// smem: A 128KB (256m x 256k fp16, sw512) | 3 X stages x 32KB (sw128) | b2 1KB
// block 512 (16 warps: 8 m-warps x 2 n-warps over 256m x 64n)
__global__ __launch_bounds__(512, 1) void pass2_kernel(const float* __restrict__ x,
                                                       float* __restrict__ out) {
    int start = blockIdx.x * TPC;
    int end = start + TPC; if (end > UNITS) end = UNITS;
    if (start >= UNITS) return;
    int nt = end - start;

    uint32_t ahb = smem_u32(dsm);
    uint32_t xsb = ahb + 131072u;
    float* b2s = (float*)(dsm + 131072 + 98304);

    int t = threadIdx.x, w = t >> 5, lane = t & 31;
    int m0 = (w >> 1) * 32;            // 8 m-warps over 256 rows
    int n0w = (w & 1) * 32;            // 2 n-warps over 64 cols

    auto loadX = [&](int u, int s) {
        int bg = u >> 10, n02 = (u & 1023) * NT2;
        const __half* src = d_xh + (size_t)bg * C_ * NNPOS + n02;
        uint32_t st = xsb + (uint32_t)s * 32768u;
#pragma unroll
        for (int i = 0; i < 4; i++) {
            int c = i * 512 + t;               // 2048 16B-chunks: 256 rows x 8
            int row = c >> 3, col16 = c & 7;
            cpasync16(st + sw128((uint32_t)row * 128u + (uint32_t)col16 * 16u),
                      src + (size_t)row * NNPOS + col16 * 8);
        }
    };

    loadX(start, 0); CP_COMMIT();
    if (nt > 1) loadX(start + 1, 1);
    CP_COMMIT();

    int cur = -1;
    for (int it = 0; it < nt; it++) {
        int u = start + it;
        int bg = u >> 10, n0t = (u & 1023) * NT2;

        if (bg != cur) {                   // load full A for batch bg (rare: <=2x)
            __syncthreads();               // prior mma/ldsm done before overwrite
            const uint4* Ah4 = (const uint4*)(d_Ah16 + (size_t)bg * C_ * CI_);
#pragma unroll
            for (int ii = 0; ii < 16; ii++) {
                int idx = ii * 512 + t;    // 8192 uint4: m = idx>>5, chunk = idx&31
                uint32_t byte = (uint32_t)(idx >> 5) * 512u + (uint32_t)(idx & 31) * 16u;
                *(uint4*)(dsm + sw512(byte)) = Ah4[idx];
            }
            if (t < 256) b2s[t] = d_b2[bg * C_ + t];
            cur = bg;
            __syncthreads();
        }
        if (it + 2 < nt) loadX(u + 2, (it + 2) % 3);
        CP_COMMIT();                       // one group per iter (may be empty)
        CP_WAIT2();                        // X tile it resident
        __syncthreads();

        uint32_t xhb = xsb + (uint32_t)(it % 3) * 32768u;

        float acc[2][4][4];
#pragma unroll
        for (int i = 0; i < 2; i++)
#pragma unroll
            for (int j = 0; j < 4; j++)
#pragma unroll
                for (int q = 0; q < 4; q++) acc[i][j][q] = 0.f;

#pragma unroll 4
        for (int ks = 0; ks < 16; ks++) {
            int k0 = ks * 16;
            uint32_t ah[2][4];
#pragma unroll
            for (int mt = 0; mt < 2; mt++) {
                uint32_t byte = (uint32_t)(m0 + mt * 16 + (lane & 15)) * 512u
                              + (uint32_t)(k0 + (lane >> 4) * 8) * 2u;
                ldsm4(ah[mt], ahb + sw512(byte));
            }
            uint32_t bf[4][2];
            int g = lane >> 3, j = lane & 7;
#pragma unroll
            for (int n2 = 0; n2 < 2; n2++) {
                uint32_t rowk = (uint32_t)(k0 + (g & 1) * 8 + j);
                uint32_t coln = (uint32_t)(n0w + n2 * 16 + (g >> 1) * 8);
                uint32_t r[4];
                ldsm4t(r, xhb + sw128(rowk * 128u + coln * 2u));
                bf[n2 * 2][0] = r[0]; bf[n2 * 2][1] = r[1];
                bf[n2 * 2 + 1][0] = r[2]; bf[n2 * 2 + 1][1] = r[3];
            }
#pragma unroll
            for (int mt = 0; mt < 2; mt++)
#pragma unroll
                for (int nt2 = 0; nt2 < 4; nt2++)
                    mma16816h(acc[mt][nt2], ah[mt], bf[nt2]);
        }

        // epilogue: out = acc + x + b2 (fp32 residual; 16 warps amortize LDG latency)
#pragma unroll
        for (int mt = 0; mt < 2; mt++) {
            int r = m0 + mt * 16 + (lane >> 2);
            float bv0 = b2s[r], bv1 = b2s[r + 8];
            size_t base0 = ((size_t)(bg * C_ + r)) * NNPOS + n0t + n0w + 2 * (lane & 3);
            size_t base1 = base0 + (size_t)8 * NNPOS;
#pragma unroll
            for (int ntt = 0; ntt < 4; ntt++) {
                float2 xv = *(const float2*)(x + base0 + ntt * 8);
                float2 o;
                o.x = acc[mt][ntt][0] + xv.x + bv0;
                o.y = acc[mt][ntt][1] + xv.y + bv0;
                *(float2*)(out + base0 + ntt * 8) = o;
                xv = *(const float2*)(x + base1 + ntt * 8);
                o.x = acc[mt][ntt][2] + xv.x + bv1;
                o.y = acc[mt][ntt][3] + xv.y + bv1;
                *(float2*)(out + base1 + ntt * 8) = o;
            }
        }
        __syncthreads();                   // all warps done reading stage before refill
    }
}

// ================= launch =================
extern "C" void kernel_launch(void* const* d_in, const int* in_sizes, int n_in,
                              void* d_out, int out_size) {
    const float* x       = (const float*)d_in[0];
    const float* g_w     = (const float*)d_in[1];
    const float* g_b     = (const float*)d_in[2];
    const float* theta_w = (const float*)d_in[3];
    const float* theta_b = (const float*)d_in[4];
    const float* phi_w   = (const float*)d_in[5];
    const float* phi_b   = (const float*)d_in[6];
    const float* W_w     = (const float*)d_in[7];
    const float* W_b     = (const float*)d_in[8];
    float* out = (float*)d_out;

    int smem1 = 3 * 32768;                  // 96KB, occ 2
    int smem2 = 131072 + 3 * 32768 + 1024;  // 225KB, occ 1 (16 warps)
    cudaFuncSetAttribute(pass1_kernel, cudaFuncAttributeMaxDynamicSharedMemorySize, smem1);
    cudaFuncSetAttribute(pass2_kernel, cudaFuncAttributeMaxDynamicSharedMemorySize, smem2);

    prepass_kernel<<<NB * C_, 256>>>(x);
    pass1_kernel<<<dim3(3, NCH1, NB), 256, smem1>>>();
    chain_kernel<<<CHAIN_BLOCKS, 256>>>(g_w, phi_w, g_b, phi_b, W_w, theta_w, theta_b, W_b);
    pass2_kernel<<<(UNITS + TPC - 1) / TPC, 512, smem2>>>(x, out);
}

// round 14
// speedup vs baseline: 1.1805x; 1.1805x over previous
#include <cuda_runtime.h>
#include <cuda_bf16.h>
#include <cuda_fp16.h>
#include <cstdint>
#include <cstddef>

#define NB 2
#define C_ 256
#define CI_ 128
#define NNPOS 65536
#define NCH1 49            // uneven k-chunks, pass1: 3 quads x 49 x 2 b = 294 CTAs
#define NT2 128            // spatial cols per pass2 tile
#define UNITS 2048         // NB * 2 mhalves * 512 ntiles
#define TPC 14             // units per CTA pass2 -> 147 CTAs (one wave)
#define CHAIN_BLOCKS 258

// ---------------- scratch (static device globals; no allocation) ----------------
__device__ __align__(16) __half   d_xh[(size_t)NB * C_ * NNPOS];       // x in fp16 (67MB)
__device__ __align__(16) float    d_Sp[(size_t)NB * NCH1 * 3 * 16384]; // partial S
__device__ __align__(16) float    d_S[NB * C_ * C_];
__device__ __align__(16) float    d_s[NB * C_];
__device__ __align__(16) float    d_gwT[C_ * CI_];        // g_w transposed [d][j]
__device__ __align__(16) float    d_T1[NB * CI_ * C_];
__device__ __align__(16) float    d_u[NB * CI_];
__device__ __align__(16) float    d_v[NB * CI_];
__device__ __align__(16) float    d_kvT[NB * CI_ * CI_];  // kv transposed [b][j][i]
__device__ __align__(16) float    d_b2[NB * C_];
__device__ __align__(16) uint32_t d_Ah16[NB * C_ * CI_];  // A fp16x2 [b][m][kpair]
__device__ unsigned d_cnt = 0;
__device__ unsigned d_gen = 0;

// ---------------- primitives ----------------
__device__ __forceinline__ uint32_t smem_u32(const void* p) {
    uint32_t a;
    asm("{ .reg .u64 t; cvta.to.shared.u64 t, %1; cvt.u32.u64 %0, t; }" : "=r"(a) : "l"(p));
    return a;
}
__device__ __forceinline__ void mma16816h(float* d, const uint32_t* a, const uint32_t* b) {
    asm volatile("mma.sync.aligned.m16n8k16.row.col.f32.f16.f16.f32 "
                 "{%0,%1,%2,%3}, {%4,%5,%6,%7}, {%8,%9}, {%0,%1,%2,%3};"
                 : "+f"(d[0]), "+f"(d[1]), "+f"(d[2]), "+f"(d[3])
                 : "r"(a[0]), "r"(a[1]), "r"(a[2]), "r"(a[3]), "r"(b[0]), "r"(b[1]));
}
__device__ __forceinline__ void ldsm4(uint32_t* r, uint32_t addr) {
    asm volatile("ldmatrix.sync.aligned.m8n8.x4.shared.b16 {%0,%1,%2,%3}, [%4];"
                 : "=r"(r[0]), "=r"(r[1]), "=r"(r[2]), "=r"(r[3]) : "r"(addr));
}
__device__ __forceinline__ void ldsm4t(uint32_t* r, uint32_t addr) {
    asm volatile("ldmatrix.sync.aligned.m8n8.x4.trans.shared.b16 {%0,%1,%2,%3}, [%4];"
                 : "=r"(r[0]), "=r"(r[1]), "=r"(r[2]), "=r"(r[3]) : "r"(addr));
}
__device__ __forceinline__ uint32_t sw128(uint32_t byte) { return byte ^ ((byte >> 3) & 0x70u); }
__device__ __forceinline__ uint32_t sw512(uint32_t byte) { return byte ^ ((byte >> 5) & 0x70u); }

__device__ __forceinline__ uint32_t packh(float x, float y) {
    __half2 h = __floats2half2_rn(x, y);
    return *(uint32_t*)&h;
}
__device__ __forceinline__ float4 f4fma(float s, float4 q, float4 a) {
    a.x += s * q.x; a.y += s * q.y; a.z += s * q.z; a.w += s * q.w;
    return a;
}
__device__ __forceinline__ void cpasync16(uint32_t dst, const void* src) {
    asm volatile("cp.async.cg.shared.global [%0], [%1], 16;" :: "r"(dst), "l"(src));
}
#define CP_COMMIT() asm volatile("cp.async.commit_group;" ::: "memory")
#define CP_WAIT1()  asm volatile("cp.async.wait_group 1;" ::: "memory")
#define CP_WAIT2()  asm volatile("cp.async.wait_group 2;" ::: "memory")

// grid-wide barrier (sense via monotonically increasing generation; replay-safe)
__device__ __forceinline__ void gridbar() {
    __syncthreads();
    if (threadIdx.x == 0) {
        __threadfence();
        unsigned g = *(volatile unsigned*)&d_gen;
        unsigned old = atomicAdd(&d_cnt, 1);
        if (old == CHAIN_BLOCKS - 1) {
            d_cnt = 0;
            __threadfence();
            atomicAdd(&d_gen, 1);
        } else {
            while (*(volatile unsigned*)&d_gen == g) { }
        }
        __threadfence();
    }
    __syncthreads();
}

extern __shared__ uint8_t dsm[];

// ================= prepass: x -> fp16 xh, rowsums =================
__global__ __launch_bounds__(256) void prepass_kernel(const float* __restrict__ x) {
    int row = blockIdx.x;                 // 0..511 = b*C_+c
    const float4* src = (const float4*)(x + (size_t)row * NNPOS);
    uint2* dst = (uint2*)(d_xh + (size_t)row * NNPOS);
    int t = threadIdx.x;
    float rs = 0.f;
#pragma unroll 4
    for (int i = t; i < NNPOS / 4; i += 256) {
        float4 v = src[i];
        rs += v.x + v.y + v.z + v.w;
        dst[i] = make_uint2(packh(v.x, v.y), packh(v.z, v.w));
    }
    __shared__ float red[256];
    red[t] = rs;
    __syncthreads();
    for (int s = 128; s > 0; s >>= 1) {
        if (t < s) red[t] += red[t + s];
        __syncthreads();
    }
    if (t == 0) d_s[row] = red[0];
}

// ================= pass 1: 3-quadrant syrk, cp.async 3-stage pipeline ============
// grid (3, NCH1, NB), block 256; smem = 3 stages x 32KB (A 16KB | B 16KB)
__global__ __launch_bounds__(256, 2) void pass1_kernel() {
    int qi = blockIdx.x, ch = blockIdx.y, b = blockIdx.z;
    int qm = qi >> 1, qn = (qi + 1) >> 1;   // 0:(0,0) 1:(0,1) 2:(1,1)
    bool diag = (qi != 1);
    int kt0 = (ch * 1024) / NCH1, kt1 = ((ch + 1) * 1024) / NCH1;
    const __half* xa = d_xh + ((size_t)(b * C_ + qm * 128)) * NNPOS;
    const __half* xb = d_xh + ((size_t)(b * C_ + qn * 128)) * NNPOS;

    int t = threadIdx.x, w = t >> 5, lane = t & 31;
    int wm = w >> 1, wn = w & 1;
    int m0 = wm * 32, n0 = wn * 64;
    uint32_t sbase = smem_u32(dsm);

    float acc[2][8][4];
#pragma unroll
    for (int i = 0; i < 2; i++)
#pragma unroll
        for (int j = 0; j < 8; j++)
#pragma unroll
            for (int q = 0; q < 4; q++) acc[i][j][q] = 0.f;

    auto load_tile = [&](int kt, int s) {
        uint32_t stA = sbase + (uint32_t)s * 32768u;
#pragma unroll
        for (int i = 0; i < 4; i++) {
            int c = i * 256 + t;
            int row = c >> 3, col16 = c & 7;
            cpasync16(stA + sw128((uint32_t)row * 128u + (uint32_t)col16 * 16u),
                      xa + (size_t)row * NNPOS + kt * 64 + col16 * 8);
        }
        if (!diag) {
            uint32_t stB = stA + 16384u;
#pragma unroll
            for (int i = 0; i < 4; i++) {
                int c = i * 256 + t;
                int row = c >> 3, col16 = c & 7;
                cpasync16(stB + sw128((uint32_t)row * 128u + (uint32_t)col16 * 16u),
                          xb + (size_t)row * NNPOS + kt * 64 + col16 * 8);
            }
        }
    };

    int nkt = kt1 - kt0;
    load_tile(kt0, 0); CP_COMMIT();
    if (nkt > 1) load_tile(kt0 + 1, 1);
    CP_COMMIT();

    for (int i = 0; i < nkt; i++) {
        if (i + 2 < nkt) load_tile(kt0 + i + 2, (i + 2) % 3);
        CP_COMMIT();                       // always one group per iter (may be empty)
        CP_WAIT2();                        // tile i resident
        __syncthreads();
        uint32_t ahb = sbase + (uint32_t)(i % 3) * 32768u;
        uint32_t bhb = diag ? ahb : ahb + 16384u;
#pragma unroll
        for (int ks = 0; ks < 4; ks++) {
            int k0 = ks * 16;
            uint32_t ah[2][4];
#pragma unroll
            for (int mt = 0; mt < 2; mt++) {
                uint32_t byte = (uint32_t)(m0 + mt * 16 + (lane & 15)) * 128u
                              + (uint32_t)(k0 + (lane >> 4) * 8) * 2u;
                ldsm4(ah[mt], ahb + sw128(byte));
            }
            uint32_t bf[8][2];
            int g = lane >> 3, j = lane & 7;
#pragma unroll
            for (int n2 = 0; n2 < 4; n2++) {
                uint32_t row = (uint32_t)(n0 + n2 * 16 + (g >> 1) * 8 + j);
                uint32_t kk  = (uint32_t)(k0 + (g & 1) * 8);
                uint32_t r[4];
                ldsm4(r, bhb + sw128(row * 128u + kk * 2u));
                bf[n2 * 2][0] = r[0]; bf[n2 * 2][1] = r[1];
                bf[n2 * 2 + 1][0] = r[2]; bf[n2 * 2 + 1][1] = r[3];
            }
#pragma unroll
            for (int mt = 0; mt < 2; mt++)
#pragma unroll
                for (int nt = 0; nt < 8; nt++)
                    mma16816h(acc[mt][nt], ah[mt], bf[nt]);
        }
        __syncthreads();
    }

    float* Sp = d_Sp + (((size_t)(b * NCH1 + ch) * 3 + qi) << 14);
#pragma unroll
    for (int mt = 0; mt < 2; mt++) {
        int r = m0 + mt * 16 + (lane >> 2);
        int c = n0 + 2 * (lane & 3);
#pragma unroll
        for (int nt = 0; nt < 8; nt++) {
            *(float2*)(Sp + (size_t)r * 128 + c + nt * 8)
                = make_float2(acc[mt][nt][0], acc[mt][nt][1]);
            *(float2*)(Sp + (size_t)(r + 8) * 128 + c + nt * 8)
                = make_float2(acc[mt][nt][2], acc[mt][nt][3]);
        }
    }
}

// ================= chain: reduce+mirror+gwt | stageA | stageB | stageC+D =========
__global__ __launch_bounds__(256, 2) void chain_kernel(
    const float* __restrict__ g_w, const float* __restrict__ phi_w,
    const float* __restrict__ g_b, const float* __restrict__ phi_b,
    const float* __restrict__ W_w, const float* __restrict__ theta_w,
    const float* __restrict__ theta_b, const float* __restrict__ W_b) {
    __shared__ __align__(16) uint8_t shraw[8448];
    int bx = blockIdx.x, t = threadIdx.x;

    // ---------- phase 1: reduce partial S (+mirror), gwt transpose ---------------
    if (bx < 96) {
        int id = bx * 256 + t;
        int b = id / 12288, rest = id % 12288;
        int slot = rest >> 12, idx4 = rest & 4095;
        const float4* p = (const float4*)d_Sp;
        size_t base = ((size_t)b * NCH1 * 3 + slot) * 4096 + idx4;
        float4 a = make_float4(0.f, 0.f, 0.f, 0.f);
#pragma unroll 7
        for (int ch = 0; ch < NCH1; ch++) {
            float4 v = p[base + (size_t)ch * 3 * 4096];
            a.x += v.x; a.y += v.y; a.z += v.z; a.w += v.w;
        }
        int ml = idx4 >> 5, c4 = idx4 & 31;
        int m = (slot == 2) ? 128 + ml : ml;
        int n4 = (slot == 0) ? c4 : 32 + c4;
        ((float4*)d_S)[(size_t)b * 16384 + m * 64 + n4] = a;
        if (slot == 1) {                       // mirror quad(1,0) = quad(0,1)^T
            float* Sb = d_S + (size_t)b * 65536;
            int nb = 128 + c4 * 4;
            Sb[(size_t)(nb + 0) * 256 + ml] = a.x;
            Sb[(size_t)(nb + 1) * 256 + ml] = a.y;
            Sb[(size_t)(nb + 2) * 256 + ml] = a.z;
            Sb[(size_t)(nb + 3) * 256 + ml] = a.w;
        }
    } else if (bx < 128) {                     // gwt: transpose g_w -> d_gwT
        float (*tile)[33] = (float (*)[33])shraw;
        int tb = bx - 96;
        int rt = tb >> 3, ct = tb & 7;
        int ty = t >> 5, tx = t & 31;
#pragma unroll
        for (int p = 0; p < 4; p++)
            tile[p * 8 + ty][tx] = g_w[(rt * 32 + p * 8 + ty) * C_ + ct * 32 + tx];
        __syncthreads();
#pragma unroll
        for (int p = 0; p < 4; p++)
            d_gwT[(ct * 32 + p * 8 + ty) * CI_ + rt * 32 + tx] = tile[tx][p * 8 + ty];
    }
    gridbar();

    // ---------- phase 2: stageA (T1 = phi_w @ S ; u,v) ---------------------------
    {
        int i = bx >> 1, b = bx & 1;
        if (i < CI_) {
            float* ph = (float*)shraw;
            float4 (*red)[64] = (float4 (*)[64])(shraw + 1024);
            ph[t] = phi_w[i * C_ + t];
            __syncthreads();
            int kq = t >> 6, jv = t & 63;
            const float4* S4 = (const float4*)(d_S + (size_t)b * 65536);
            float4 a = make_float4(0.f, 0.f, 0.f, 0.f);
#pragma unroll 8
            for (int c = kq * 64; c < kq * 64 + 64; c++)
                a = f4fma(ph[c], S4[c * 64 + jv], a);
            red[kq][jv] = a;
            __syncthreads();
            if (kq == 0) {
                float4 s0 = red[0][jv], s1 = red[1][jv], s2 = red[2][jv], s3 = red[3][jv];
                float4 o;
                o.x = s0.x + s1.x + s2.x + s3.x; o.y = s0.y + s1.y + s2.y + s3.y;
                o.z = s0.z + s1.z + s2.z + s3.z; o.w = s0.w + s1.w + s2.w + s3.w;
                ((float4*)(d_T1 + ((size_t)b * CI_ + i) * C_))[jv] = o;
            }
        } else if (i == CI_) {
            float* ss = (float*)shraw;
            ss[t] = d_s[b * C_ + t];
            __syncthreads();
            int hf = t >> 7, ii = t & 127;
            const float4* wr = (const float4*)((hf ? g_w : phi_w) + ii * C_);
            const float4* sv = (const float4*)ss;
            float acc = 0.f;
#pragma unroll 8
            for (int q = 0; q < 64; q++) {
                float4 wv = wr[q], s4 = sv[q];
                acc += wv.x * s4.x + wv.y * s4.y + wv.z * s4.z + wv.w * s4.w;
            }
            if (hf) d_v[b * CI_ + ii] = acc; else d_u[b * CI_ + ii] = acc;
        }
    }
    gridbar();

    // ---------- phase 3: stageB (kvT) --------------------------------------------
    if (bx < 256) {
        int i = bx >> 1, b = bx & 1;
        float* t1 = (float*)shraw;
        float4 (*red)[32] = (float4 (*)[32])(shraw + 1024);
        t1[t] = d_T1[((size_t)b * CI_ + i) * C_ + t];
        __syncthreads();
        int kq = t >> 5, jv = t & 31;
        const float4* Q = (const float4*)d_gwT;
        float4 a = make_float4(0.f, 0.f, 0.f, 0.f);
#pragma unroll 8
        for (int d = kq * 32; d < kq * 32 + 32; d++)
            a = f4fma(t1[d], Q[d * 32 + jv], a);
        red[kq][jv] = a;
        __syncthreads();
        if (kq == 0) {
            float4 o = make_float4(0.f, 0.f, 0.f, 0.f);
#pragma unroll
            for (int q = 0; q < 8; q++) {
                float4 v = red[q][jv];
                o.x += v.x; o.y += v.y; o.z += v.z; o.w += v.w;
            }
            float ui = d_u[b * CI_ + i], pb = phi_b[i];
            float4 gb = ((const float4*)g_b)[jv];
            float4 vv = ((const float4*)(d_v + b * CI_))[jv];
            o.x += ui * gb.x + pb * vv.x + 65536.0f * pb * gb.x;
            o.y += ui * gb.y + pb * vv.y + 65536.0f * pb * gb.y;
            o.z += ui * gb.z + pb * vv.z + 65536.0f * pb * gb.z;
            o.w += ui * gb.w + pb * vv.w + 65536.0f * pb * gb.w;
            float* kt = d_kvT + (size_t)b * CI_ * CI_;
            kt[(jv * 4 + 0) * CI_ + i] = o.x;
            kt[(jv * 4 + 1) * CI_ + i] = o.y;
            kt[(jv * 4 + 2) * CI_ + i] = o.z;
            kt[(jv * 4 + 3) * CI_ + i] = o.w;
        }
    }
    gridbar();

    // ---------- phase 4: stageC+D fused (per m-row) ------------------------------
    if (bx < 256) {
        int m = bx;
        float*  ww   = (float*)shraw;
        float4 (*red)[32] = (float4 (*)[32])(shraw + 512);
        float*  mmv  = (float*)(shraw + 4608);
        float*  bred = (float*)(shraw + 5120);
        float4 (*redD)[64] = (float4 (*)[64])(shraw + 512);
        for (int b = 0; b < NB; b++) {
            if (t < CI_) ww[t] = W_w[m * CI_ + t];
            __syncthreads();
            int kq = t >> 5, iv = t & 31;
            const float4* Q = (const float4*)(d_kvT + (size_t)b * CI_ * CI_);
            float4 a = make_float4(0.f, 0.f, 0.f, 0.f);
#pragma unroll 8
            for (int j = kq * 16; j < kq * 16 + 16; j++)
                a = f4fma(ww[j], Q[j * 32 + iv], a);
            red[kq][iv] = a;
            __syncthreads();
            if (kq == 0) {
                float4 o = make_float4(0.f, 0.f, 0.f, 0.f);
#pragma unroll
                for (int q = 0; q < 8; q++) {
                    float4 v = red[q][iv];
                    o.x += v.x; o.y += v.y; o.z += v.z; o.w += v.w;
                }
                const float inv = 1.0f / 65536.0f;
                mmv[iv * 4 + 0] = o.x * inv;
                mmv[iv * 4 + 1] = o.y * inv;
                mmv[iv * 4 + 2] = o.z * inv;
                mmv[iv * 4 + 3] = o.w * inv;
            }
            __syncthreads();
            int kq2 = t >> 6, jv2 = t & 63;
            const float4* Qt = (const float4*)theta_w;
            float4 ad = make_float4(0.f, 0.f, 0.f, 0.f);
#pragma unroll 8
            for (int i = kq2 * 32; i < kq2 * 32 + 32; i++)
                ad = f4fma(mmv[i], Qt[i * 64 + jv2], ad);
            redD[kq2][jv2] = ad;
            if (t < CI_) bred[t] = mmv[t] * theta_b[t];
            __syncthreads();
            if (kq2 == 0) {
                float4 s0 = redD[0][jv2], s1 = redD[1][jv2], s2 = redD[2][jv2], s3 = redD[3][jv2];
                float a0 = s0.x + s1.x + s2.x + s3.x, a1 = s0.y + s1.y + s2.y + s3.y;
                float a2 = s0.z + s1.z + s2.z + s3.z, a3 = s0.w + s1.w + s2.w + s3.w;
                size_t base = ((size_t)b * C_ + m) * CI_ + jv2 * 2;
                d_Ah16[base]     = packh(a0, a1);
                d_Ah16[base + 1] = packh(a2, a3);
            }
            for (int s2v = 64; s2v > 0; s2v >>= 1) {
                if (t < s2v) bred[t] += bred[t + s2v];
                __syncthreads();
            }
            if (t == 0) d_b2[b * C_ + m] = bred[0] + W_b[m];
            __syncthreads();
        }
    }
}

// ================= pass 2: out = x + A x + b2 (512 thr, smem fp16 residual) ======
// smem: A 64KB (sw512) | 2 X stages x 64KB (two 32KB 64-col halves) | b2 512B
__global__ __launch_bounds__(512, 1) void pass2_kernel(float* __restrict__ out) {
    int start = blockIdx.x * TPC;
    int end = start + TPC; if (end > UNITS) end = UNITS;
    if (start >= UNITS) return;
    int nt = end - start;

    uint32_t ahb = smem_u32(dsm);
    uint32_t xsb = ahb + 65536u;
    float* b2s = (float*)(dsm + 65536 + 131072);

    int t = threadIdx.x, w = t >> 5, lane = t & 31;
    int m0 = (w >> 2) * 32;            // 4 m-warps over 128 rows
    int n0w = (w & 3) * 32;            // 4 n-warps over 128 cols

    auto loadX = [&](int u, int s) {
        int bg = u >> 10, n02 = (u & 511) * NT2;
        const __half* src = d_xh + (size_t)bg * C_ * NNPOS + n02;
        uint32_t st = xsb + (uint32_t)s * 65536u;
#pragma unroll
        for (int i = 0; i < 8; i++) {
            int c = i * 512 + t;               // 4096 16B-chunks: 256 rows x 16
            int row = c >> 4, col16 = c & 15;
            uint32_t half = (uint32_t)(col16 >> 3);
            uint32_t c8 = (uint32_t)(col16 & 7);
            cpasync16(st + half * 32768u + sw128((uint32_t)row * 128u + c8 * 16u),
                      src + (size_t)row * NNPOS + col16 * 8);
        }
    };

    loadX(start, 0); CP_COMMIT();

    int cur = -1;
    for (int it = 0; it < nt; it++) {
        int u = start + it;
        int bg = u >> 10, mh = (u >> 9) & 1, n0t = (u & 511) * NT2;

        if ((u >> 9) != cur) {             // load A m-half (prev mma synced below)
            const uint4* Ah4 = (const uint4*)(d_Ah16 + ((size_t)(bg * C_ + mh * 128)) * CI_);
#pragma unroll
            for (int ii = 0; ii < 8; ii++) {
                int idx = ii * 512 + t;
                uint32_t byte = (uint32_t)(idx >> 5) * 512u + (uint32_t)(idx & 31) * 16u;
                *(uint4*)(dsm + sw512(byte)) = Ah4[idx];
            }
            if (t < 128) b2s[t] = d_b2[bg * C_ + mh * 128 + t];
            cur = u >> 9;
            __syncthreads();
        }
        if (it + 1 < nt) loadX(u + 1, (it + 1) & 1);
        CP_COMMIT();
        CP_WAIT1();                        // X tile it resident
        __syncthreads();

        uint32_t xhb = xsb + (uint32_t)(it & 1) * 65536u;

        float acc[2][4][4];
#pragma unroll
        for (int i = 0; i < 2; i++)
#pragma unroll
            for (int j = 0; j < 4; j++)
#pragma unroll
                for (int q = 0; q < 4; q++) acc[i][j][q] = 0.f;

#pragma unroll 4
        for (int ks = 0; ks < 16; ks++) {
            int k0 = ks * 16;
            uint32_t ah[2][4];
#pragma unroll
            for (int mt = 0; mt < 2; mt++) {
                uint32_t byte = (uint32_t)(m0 + mt * 16 + (lane & 15)) * 512u
                              + (uint32_t)(k0 + (lane >> 4) * 8) * 2u;
                ldsm4(ah[mt], ahb + sw512(byte));
            }
            uint32_t bf[4][2];
            int g = lane >> 3, j = lane & 7;
#pragma unroll
            for (int n2 = 0; n2 < 2; n2++) {
                uint32_t rowk = (uint32_t)(k0 + (g & 1) * 8 + j);
                uint32_t cg = (uint32_t)(n0w + n2 * 16 + (g >> 1) * 8);
                uint32_t half = cg >> 6, coln = cg & 63u;
                uint32_t r[4];
                ldsm4t(r, xhb + half * 32768u + sw128(rowk * 128u + coln * 2u));
                bf[n2 * 2][0] = r[0]; bf[n2 * 2][1] = r[1];
                bf[n2 * 2 + 1][0] = r[2]; bf[n2 * 2 + 1][1] = r[3];
            }
#pragma unroll
            for (int mt = 0; mt < 2; mt++)
#pragma unroll
                for (int nt2 = 0; nt2 < 4; nt2++)
                    mma16816h(acc[mt][nt2], ah[mt], bf[nt2]);
        }

        // epilogue: out = acc + fp16(x) + b2 — residual read from the smem X tile
#pragma unroll
        for (int mt = 0; mt < 2; mt++) {
            int r = m0 + mt * 16 + (lane >> 2);
            float bv0 = b2s[r], bv1 = b2s[r + 8];
            uint32_t row0 = (uint32_t)(mh * 128 + r);
            size_t base0 = ((size_t)(bg * C_ + mh * 128 + r)) * NNPOS + n0t + n0w + 2 * (lane & 3);
            size_t base1 = base0 + (size_t)8 * NNPOS;
#pragma unroll
            for (int ntt = 0; ntt < 4; ntt++) {
                uint32_t cg = (uint32_t)(n0w + 2 * (lane & 3) + ntt * 8);
                uint32_t half = cg >> 6, coln = cg & 63u;
                uint32_t hoff = xhb + half * 32768u;
                __half2 h0 = *(__half2*)(uintptr_t)0;   // placeholder (replaced below)
                uint32_t a0, a1;
                asm volatile("ld.shared.b32 %0, [%1];" : "=r"(a0)
                             : "r"(hoff + sw128(row0 * 128u + coln * 2u)));
                asm volatile("ld.shared.b32 %0, [%1];" : "=r"(a1)
                             : "r"(hoff + sw128((row0 + 8u) * 128u + coln * 2u)));
                float2 xv0 = __half22float2(*(__half2*)&a0);
                float2 xv1 = __half22float2(*(__half2*)&a1);
                (void)h0;
                float2 o;
                o.x = acc[mt][ntt][0] + xv0.x + bv0;
                o.y = acc[mt][ntt][1] + xv0.y + bv0;
                *(float2*)(out + base0 + ntt * 8) = o;
                o.x = acc[mt][ntt][2] + xv1.x + bv1;
                o.y = acc[mt][ntt][3] + xv1.y + bv1;
                *(float2*)(out + base1 + ntt * 8) = o;
            }
        }
        __syncthreads();                   // protect stage before overwrite (2-deep ring)
    }
}

// ================= launch =================
extern "C" void kernel_launch(void* const* d_in, const int* in_sizes, int n_in,
                              void* d_out, int out_size) {
    const float* x       = (const float*)d_in[0];
    const float* g_w     = (const float*)d_in[1];
    const float* g_b     = (const float*)d_in[2];
    const float* theta_w = (const float*)d_in[3];
    const float* theta_b = (const float*)d_in[4];
    const float* phi_w   = (const float*)d_in[5];
    const float* phi_b   = (const float*)d_in[6];
    const float* W_w     = (const float*)d_in[7];
    const float* W_b     = (const float*)d_in[8];
    float* out = (float*)d_out;

    int smem1 = 3 * 32768;                  // 96KB, occ 2
    int smem2 = 65536 + 131072 + 1024;      // ~193KB, occ 1 (16 warps)
    cudaFuncSetAttribute(pass1_kernel, cudaFuncAttributeMaxDynamicSharedMemorySize, smem1);
    cudaFuncSetAttribute(pass2_kernel, cudaFuncAttributeMaxDynamicSharedMemorySize, smem2);

    prepass_kernel<<<NB * C_, 256>>>(x);
    pass1_kernel<<<dim3(3, NCH1, NB), 256, smem1>>>();
    chain_kernel<<<CHAIN_BLOCKS, 256>>>(g_w, phi_w, g_b, phi_b, W_w, theta_w, theta_b, W_b);
    pass2_kernel<<<(UNITS + TPC - 1) / TPC, 512, smem2>>>(out);
}